// round 6
// baseline (speedup 1.0000x reference)
#include <cuda_runtime.h>
#include <cstdint>
#include <math.h>

#define EPS 1e-4f
#define B_SZ   64
#define C_SZ   512
#define HW_SZ  196
#define P_SZ   2000
#define MT     128
#define NT     112
#define KC     32
#define NSTAGE 16
#define APITCH 36
#define BPITCH 120
#define EPITCH 113

#define A_STG (MT*APITCH)              // 4608 floats
#define B_STG (KC*BPITCH)              // 3840 floats
#define STG_FLOATS (A_STG + B_STG)     // 8448 floats per stage
#define SMEM_FLOATS (3*STG_FLOATS)     // 25344 floats (3-stage ring)
#define SMEM_BYTES  (SMEM_FLOATS*4)    // 101376 B

// global scratch for norms (no cudaMalloc allowed)
__device__ float g_x2p[8][B_SZ*HW_SZ];
__device__ float g_x2[B_SZ*HW_SZ];
__device__ float g_p2[2048];

static __device__ __forceinline__ uint32_t s2u(const void* p) {
    uint32_t a;
    asm("{ .reg .u64 t; cvta.to.shared.u64 t, %1; cvt.u32.u64 %0, t; }"
        : "=r"(a) : "l"(p));
    return a;
}

static __device__ __forceinline__ void cpa16(uint32_t dst, const void* src, int sz) {
    asm volatile("cp.async.cg.shared.global [%0], [%1], 16, %2;"
                 :: "r"(dst), "l"(src), "r"(sz));
}

static __device__ __forceinline__ void ldsm4(uint32_t& r0, uint32_t& r1,
                                             uint32_t& r2, uint32_t& r3, uint32_t a) {
    asm volatile("ldmatrix.sync.aligned.m8n8.x4.shared.b16 {%0,%1,%2,%3}, [%4];"
                 : "=r"(r0), "=r"(r1), "=r"(r2), "=r"(r3) : "r"(a));
}

static __device__ __forceinline__ void mma_tf32(
    float& c0, float& c1, float& c2, float& c3,
    uint32_t a0, uint32_t a1, uint32_t a2, uint32_t a3, float b0, float b1)
{
    asm volatile(
        "mma.sync.aligned.m16n8k8.row.col.f32.tf32.tf32.f32 "
        "{%0,%1,%2,%3}, {%4,%5,%6,%7}, {%8,%9}, {%0,%1,%2,%3};"
        : "+f"(c0), "+f"(c1), "+f"(c2), "+f"(c3)
        : "r"(a0), "r"(a1), "r"(a2), "r"(a3),
          "r"(__float_as_uint(b0)), "r"(__float_as_uint(b1)));
}

// ---- norm precompute (deterministic two-pass, no atomics) ----
__global__ void x2_part(const float* __restrict__ x) {
    int i = blockIdx.x * 256 + threadIdx.x;
    if (i >= B_SZ * HW_SZ) return;
    int b = i / HW_SZ, hw = i - b * HW_SZ;
    int z = blockIdx.y;
    const float* px = x + (size_t)b * C_SZ * HW_SZ + (size_t)z * 64 * HW_SZ + hw;
    float s = 0.f;
#pragma unroll 16
    for (int c = 0; c < 64; c++) {
        float v = px[(size_t)c * HW_SZ];
        s = fmaf(v, v, s);
    }
    g_x2p[z][i] = s;
}

__global__ void x2_reduce() {
    int i = blockIdx.x * 256 + threadIdx.x;
    if (i >= B_SZ * HW_SZ) return;
    float s = 0.f;
#pragma unroll
    for (int z = 0; z < 8; z++) s += g_x2p[z][i];
    g_x2[i] = s;
}

__global__ void p2_k(const float* __restrict__ p) {
    int row  = blockIdx.x * 8 + (threadIdx.x >> 5);
    int lane = threadIdx.x & 31;
    float s = 0.f;
    if (row < P_SZ) {
        const float* pr = p + (size_t)row * C_SZ;
#pragma unroll
        for (int t = lane; t < C_SZ; t += 32) {
            float v = pr[t];
            s = fmaf(v, v, s);
        }
    }
#pragma unroll
    for (int o = 16; o > 0; o >>= 1)
        s += __shfl_down_sync(0xffffffffu, s, o);
    if (row < P_SZ && lane == 0) g_p2[row] = s;
}

// ---- main fused GEMM + epilogue ----
__global__ __launch_bounds__(256, 2) void proto_mma(
    const float* __restrict__ x,
    const float* __restrict__ p,
    float* __restrict__ out)
{
    extern __shared__ float smf[];
    const uint32_t sb = s2u(smf);
    const int tid  = threadIdx.x;
    const int wid  = tid >> 5;
    const int lane = tid & 31;
    const int qr   = lane >> 2;
    const int qc   = lane & 3;
    const int nb   = blockIdx.x * NT;
    const int mb   = blockIdx.y * MT;
    const int b    = blockIdx.z;
    const int mw   = (wid >> 1) * 32;
    const int nw   = (wid & 1) * 56;
    const float* xb = x + (size_t)b * C_SZ * HW_SZ;

    // ldmatrix per-lane source row/col within A tile
    const int lrow = mw + (lane & 7) + 8 * ((lane >> 3) & 1);
    const int lcol = 4 * (lane >> 4);

    // per-thread load coordinates (fixed across stages)
    const int a_row = tid >> 3, a_j = tid & 7;            // +l*256: rows +32
    const int a_sz  = 16;                                  // mb+row < 2000 always (mb<=1920, row<128)
    const float* a_src0 = p + (size_t)(mb + a_row) * C_SZ + a_j * 4;

    float acc[2][7][4];
#pragma unroll
    for (int i = 0; i < 2; i++)
#pragma unroll
        for (int j = 0; j < 7; j++)
#pragma unroll
            for (int r = 0; r < 4; r++) acc[i][j][r] = 0.f;

    auto load_stage = [&](int s) {
        const int buf = s % 3;
        const int kt  = s * KC;
        const uint32_t sA = sb + buf * STG_FLOATS * 4;
        const uint32_t sB = sA + A_STG * 4;
#pragma unroll
        for (int l = 0; l < 4; l++) {
            int row = a_row + l * 32;
            cpa16(sA + (row * APITCH + a_j * 4) * 4,
                  a_src0 + (size_t)l * 32 * C_SZ + kt, a_sz);
        }
#pragma unroll
        for (int l = 0; l < 4; l++) {
            int idx = tid + l * 256;
            if (idx < 896) {
                int k = idx / 28, q = idx - k * 28;
                int n0 = nb + q * 4;
                int sz = (n0 <= HW_SZ - 4) ? 16 : 0;
                cpa16(sB + (k * BPITCH + q * 4) * 4,
                      xb + (size_t)(kt + k) * HW_SZ + n0, sz);
            }
        }
    };

    load_stage(0);
    asm volatile("cp.async.commit_group;" ::: "memory");
    load_stage(1);
    asm volatile("cp.async.commit_group;" ::: "memory");

    for (int s = 0; s < NSTAGE; s++) {
        asm volatile("cp.async.wait_group 1;" ::: "memory");
        __syncthreads();
        if (s + 2 < NSTAGE) load_stage(s + 2);
        asm volatile("cp.async.commit_group;" ::: "memory");

        const int buf = s % 3;
        const uint32_t sA = sb + buf * STG_FLOATS * 4;
        const float* Bb = smf + buf * STG_FLOATS + A_STG;
        const uint32_t aAddr = sA + (lrow * APITCH + lcol) * 4;
        const float* bp = Bb + qc * BPITCH + nw + qr;

#pragma unroll
        for (int ks = 0; ks < 4; ks++) {
            const int k8 = ks * 8;
            uint32_t af[2][4];
            ldsm4(af[0][0], af[0][1], af[0][2], af[0][3], aAddr + k8 * 4);
            ldsm4(af[1][0], af[1][1], af[1][2], af[1][3],
                  aAddr + (16 * APITCH + k8) * 4);
#pragma unroll
            for (int j = 0; j < 7; j++) {
                float b0 = bp[ k8      * BPITCH + 8*j];
                float b1 = bp[(k8 + 4) * BPITCH + 8*j];
                mma_tf32(acc[0][j][0], acc[0][j][1], acc[0][j][2], acc[0][j][3],
                         af[0][0], af[0][1], af[0][2], af[0][3], b0, b1);
                mma_tf32(acc[1][j][0], acc[1][j][1], acc[1][j][2], acc[1][j][3],
                         af[1][0], af[1][1], af[1][2], af[1][3], b0, b1);
            }
        }
    }
    __syncthreads();   // all compute done before epilogue reuses smem

    // ---- fetch precomputed norms ----
    float pa2v[2][2];
#pragma unroll
    for (int i = 0; i < 2; i++)
#pragma unroll
        for (int h = 0; h < 2; h++) {
            int row = mb + mw + 16*i + 8*h + qr;
            pa2v[i][h] = (row < P_SZ) ? g_p2[row] : 0.f;
        }
    float x2v[7][2];
#pragma unroll
    for (int j = 0; j < 7; j++)
#pragma unroll
        for (int h = 0; h < 2; h++) {
            int n = nb + nw + 8*j + qc*2 + h;
            x2v[j][h] = (n < HW_SZ) ? g_x2[b * HW_SZ + n] : 0.f;
        }

    // ---- epilogue: act = log((dist+1)/(dist+EPS)) -> smem transpose ----
    float* Es = smf;   // 128 x 113 floats = 14464 <= 25344
#pragma unroll
    for (int i = 0; i < 2; i++)
#pragma unroll
        for (int j = 0; j < 7; j++)
#pragma unroll
            for (int r = 0; r < 4; r++) {
                int rl = mw + 16*i + qr + (r >> 1) * 8;
                int cl = nw + 8*j + qc * 2 + (r & 1);
                float dist = fmaxf(x2v[j][r & 1] - 2.f * acc[i][j][r] + pa2v[i][r >> 1], 0.f);
                Es[rl * EPITCH + cl] = logf((dist + 1.0f) / (dist + EPS));
            }
    __syncthreads();

    // ---- coalesced store ----
    if (tid < 224) {
        const int col  = tid % NT;
        const int row0 = tid / NT;
        const int n    = nb + col;
        if (n < HW_SZ) {
#pragma unroll 4
            for (int row = row0; row < MT; row += 2) {
                int m = mb + row;
                if (m < P_SZ)
                    out[((size_t)b * P_SZ + m) * HW_SZ + n] = Es[row * EPITCH + col];
            }
        }
    }
}

extern "C" void kernel_launch(void* const* d_in, const int* in_sizes, int n_in,
                              void* d_out, int out_size) {
    const float* x = (const float*)d_in[0];   // (64, 512, 14, 14)
    const float* p = (const float*)d_in[1];   // (2000, 512, 1, 1)
    float* out = (float*)d_out;               // (64, 2000, 14, 14)

    x2_part<<<dim3(49, 8), 256>>>(x);
    x2_reduce<<<49, 256>>>();
    p2_k<<<250, 256>>>(p);

    cudaFuncSetAttribute(proto_mma, cudaFuncAttributeMaxDynamicSharedMemorySize, SMEM_BYTES);
    dim3 grid(2, 16, B_SZ);
    proto_mma<<<grid, 256, SMEM_BYTES>>>(x, p, out);
}

// round 7
// speedup vs baseline: 1.4107x; 1.4107x over previous
#include <cuda_runtime.h>
#include <cuda_bf16.h>
#include <cstdint>
#include <math.h>

#define EPS 1e-4f
#define B_SZ   64
#define C_SZ   512
#define HW_SZ  196
#define P_SZ   2000
#define MT     128
#define NT     112
#define KC     32
#define NSTAGE 16
#define NBUF   4
#define EPITCH 113

#define AP 80                          // A row pitch bytes (32 bf16 = 64B data)
#define BP 80                          // B row pitch bytes
#define A_STG_B (MT*AP)                // 10240
#define B_STG_B (NT*BP)                // 8960
#define STG_B   (A_STG_B + B_STG_B)    // 19200
#define SMEM_BYTES (NBUF*STG_B)        // 76800

// global scratch (no cudaMalloc allowed); .bss zero-init
__device__ __nv_bfloat16 g_xb16t[B_SZ * HW_SZ * C_SZ];   // [b][hw][c]
__device__ __nv_bfloat16 g_pb16[2048 * C_SZ];            // [row][c], rows>=2000 zero
__device__ float g_x2[B_SZ * HW_SZ];
__device__ float g_p2[2048];

static __device__ __forceinline__ uint32_t s2u(const void* p) {
    uint32_t a;
    asm("{ .reg .u64 t; cvta.to.shared.u64 t, %1; cvt.u32.u64 %0, t; }"
        : "=r"(a) : "l"(p));
    return a;
}

static __device__ __forceinline__ void cpa16(uint32_t dst, const void* src, int sz) {
    asm volatile("cp.async.cg.shared.global [%0], [%1], 16, %2;"
                 :: "r"(dst), "l"(src), "r"(sz));
}

static __device__ __forceinline__ void ldsm4(uint32_t& r0, uint32_t& r1,
                                             uint32_t& r2, uint32_t& r3, uint32_t a) {
    asm volatile("ldmatrix.sync.aligned.m8n8.x4.shared.b16 {%0,%1,%2,%3}, [%4];"
                 : "=r"(r0), "=r"(r1), "=r"(r2), "=r"(r3) : "r"(a));
}

static __device__ __forceinline__ void mma_bf16(
    float& c0, float& c1, float& c2, float& c3,
    uint32_t a0, uint32_t a1, uint32_t a2, uint32_t a3,
    uint32_t b0, uint32_t b1)
{
    asm volatile(
        "mma.sync.aligned.m16n8k16.row.col.f32.bf16.bf16.f32 "
        "{%0,%1,%2,%3}, {%4,%5,%6,%7}, {%8,%9}, {%0,%1,%2,%3};"
        : "+f"(c0), "+f"(c1), "+f"(c2), "+f"(c3)
        : "r"(a0), "r"(a1), "r"(a2), "r"(a3), "r"(b0), "r"(b1));
}

// ---- prefix 1: x -> bf16 transposed [b][hw][c], + exact fp32 x2 ----
__global__ __launch_bounds__(256) void x_conv(const float* __restrict__ x) {
    __shared__ float sm[64 * 29];       // [c][hw] tile, pitch 29
    __shared__ float ps[28 * 65];       // per-(hw,c) square partials
    const int tid = threadIdx.x;
    const int b   = blockIdx.y;
    const int hw0 = blockIdx.x * 28;
    const float* xb = x + (size_t)b * C_SZ * HW_SZ;
    __nv_bfloat16* ob = g_xb16t + ((size_t)b * HW_SZ + hw0) * C_SZ;

    for (int c0 = 0; c0 < C_SZ; c0 += 64) {
#pragma unroll
        for (int l = 0; l < 7; l++) {
            int idx = tid + l * 256;
            int c = idx / 28, hw = idx - c * 28;
            sm[c * 29 + hw] = xb[(size_t)(c0 + c) * HW_SZ + hw0 + hw];
        }
        __syncthreads();
#pragma unroll
        for (int l = 0; l < 7; l++) {
            int idx = tid + l * 256;
            int hw = idx >> 6, c = idx & 63;
            float v = sm[c * 29 + hw];
            ob[(size_t)hw * C_SZ + c0 + c] = __float2bfloat16(v);
            if (c0 == 0) ps[hw * 65 + c] = v * v;
            else         ps[hw * 65 + c] += v * v;
        }
        __syncthreads();
    }
    if (tid < 28) {
        float s = 0.f;
#pragma unroll
        for (int c = 0; c < 64; c++) s += ps[tid * 65 + c];
        g_x2[b * HW_SZ + hw0 + tid] = s;
    }
}

// ---- prefix 2: p -> bf16 + p2 ----
__global__ __launch_bounds__(256) void p_conv(const float* __restrict__ p) {
    int row  = blockIdx.x * 8 + (threadIdx.x >> 5);
    int lane = threadIdx.x & 31;
    float s = 0.f;
    if (row < P_SZ) {
        const float* pr = p + (size_t)row * C_SZ;
        __nv_bfloat16* pw = g_pb16 + (size_t)row * C_SZ;
#pragma unroll
        for (int t = lane; t < C_SZ; t += 32) {
            float v = pr[t];
            pw[t] = __float2bfloat16(v);
            s = fmaf(v, v, s);
        }
    }
#pragma unroll
    for (int o = 16; o > 0; o >>= 1)
        s += __shfl_down_sync(0xffffffffu, s, o);
    if (row < P_SZ && lane == 0) g_p2[row] = s;
}

// ---- main fused bf16 GEMM + epilogue ----
__global__ __launch_bounds__(256, 2) void proto_mma(
    const __nv_bfloat16* __restrict__ xt,   // g_xb16t
    const __nv_bfloat16* __restrict__ pb,   // g_pb16
    float* __restrict__ out)
{
    extern __shared__ char smc[];
    const uint32_t sb = s2u(smc);
    const int tid  = threadIdx.x;
    const int wid  = tid >> 5;
    const int lane = tid & 31;
    const int qr   = lane >> 2;
    const int qc   = lane & 3;
    const int nb   = blockIdx.x * NT;
    const int mb   = blockIdx.y * MT;
    const int b    = blockIdx.z;
    const int mw   = (wid >> 1) * 32;
    const int nw   = (wid & 1) * 56;
    const __nv_bfloat16* xbase = xt + (size_t)b * HW_SZ * C_SZ;

    // ldmatrix lane address components within A tile
    const int lrow  = mw + (lane & 7) + 8 * ((lane >> 3) & 1);
    const int lcolB = (lane >> 4) << 4;     // +16B for col-half

    // loader coords
    const int a_row = tid >> 2, a_c = tid & 3;            // +256 -> rows +64
    const int b_n   = tid >> 2, b_c = tid & 3;            // idx<448
    const __nv_bfloat16* a_src0 = pb + (size_t)(mb + a_row) * C_SZ + a_c * 8;
    const __nv_bfloat16* a_src1 = a_src0 + (size_t)64 * C_SZ;

    float acc[2][7][4];
#pragma unroll
    for (int i = 0; i < 2; i++)
#pragma unroll
        for (int j = 0; j < 7; j++)
#pragma unroll
            for (int r = 0; r < 4; r++) acc[i][j][r] = 0.f;

    auto load_stage = [&](int s) {
        const int buf = s & (NBUF - 1);
        const int kt  = s * KC;
        const uint32_t sA = sb + buf * STG_B;
        const uint32_t sB = sA + A_STG_B;
        // A: 128 rows x 4 chunks (512), 2 per thread
        cpa16(sA + a_row * AP + a_c * 16, a_src0 + kt, 16);
        cpa16(sA + (a_row + 64) * AP + a_c * 16, a_src1 + kt, 16);
        // B: 112 rows x 4 chunks (448): tid + (tid<192 ? +256)
        {
            int hw = nb + b_n;
            int sz = (hw < HW_SZ) ? 16 : 0;
            cpa16(sB + b_n * BP + b_c * 16,
                  xbase + (size_t)hw * C_SZ + kt + b_c * 8, sz);
        }
        if (tid < 192) {
            int idx = tid + 256;
            int n = idx >> 2, c = idx & 3;
            int hw = nb + n;
            int sz = (hw < HW_SZ) ? 16 : 0;
            cpa16(sB + n * BP + c * 16,
                  xbase + (size_t)hw * C_SZ + kt + c * 8, sz);
        }
    };

#pragma unroll
    for (int s = 0; s < 3; s++) {
        load_stage(s);
        asm volatile("cp.async.commit_group;" ::: "memory");
    }

    for (int s = 0; s < NSTAGE; s++) {
        asm volatile("cp.async.wait_group 2;" ::: "memory");
        __syncthreads();
        if (s + 3 < NSTAGE) load_stage(s + 3);
        asm volatile("cp.async.commit_group;" ::: "memory");

        const int buf = s & (NBUF - 1);
        const uint32_t sA = sb + buf * STG_B;
        const uint32_t sB = sA + A_STG_B;
        const uint32_t aAddr = sA + lrow * AP + lcolB;
        const uint32_t bAddr = sB + (nw + qr) * BP + 4 * qc;

#pragma unroll
        for (int ks = 0; ks < 2; ks++) {
            uint32_t af[2][4];
            ldsm4(af[0][0], af[0][1], af[0][2], af[0][3], aAddr + ks * 32);
            ldsm4(af[1][0], af[1][1], af[1][2], af[1][3],
                  aAddr + 16 * AP + ks * 32);
            uint32_t bb[7][2];
#pragma unroll
            for (int j = 0; j < 7; j++) {
                uint32_t ba = bAddr + j * 8 * BP + ks * 32;
                asm volatile("ld.shared.b32 %0, [%1];"      : "=r"(bb[j][0]) : "r"(ba));
                asm volatile("ld.shared.b32 %0, [%1+16];"   : "=r"(bb[j][1]) : "r"(ba));
            }
#pragma unroll
            for (int j = 0; j < 7; j++) {
                mma_bf16(acc[0][j][0], acc[0][j][1], acc[0][j][2], acc[0][j][3],
                         af[0][0], af[0][1], af[0][2], af[0][3], bb[j][0], bb[j][1]);
                mma_bf16(acc[1][j][0], acc[1][j][1], acc[1][j][2], acc[1][j][3],
                         af[1][0], af[1][1], af[1][2], af[1][3], bb[j][0], bb[j][1]);
            }
        }
    }
    __syncthreads();   // compute done before epilogue reuses smem

    // ---- norms ----
    float pa2v[2][2];
#pragma unroll
    for (int i = 0; i < 2; i++)
#pragma unroll
        for (int h = 0; h < 2; h++) {
            int row = mb + mw + 16*i + 8*h + qr;
            pa2v[i][h] = (row < P_SZ) ? g_p2[row] : 0.f;
        }
    float x2v[7][2];
#pragma unroll
    for (int j = 0; j < 7; j++)
#pragma unroll
        for (int h = 0; h < 2; h++) {
            int n = nb + nw + 8*j + qc*2 + h;
            x2v[j][h] = (n < HW_SZ) ? g_x2[b * HW_SZ + n] : 0.f;
        }

    // ---- epilogue -> smem transpose ----
    float* Es = (float*)smc;   // 128 x 113 fp32 = 57856 <= 76800
#pragma unroll
    for (int i = 0; i < 2; i++)
#pragma unroll
        for (int j = 0; j < 7; j++)
#pragma unroll
            for (int r = 0; r < 4; r++) {
                int rl = mw + 16*i + qr + (r >> 1) * 8;
                int cl = nw + 8*j + qc * 2 + (r & 1);
                float dist = fmaxf(x2v[j][r & 1] - 2.f * acc[i][j][r] + pa2v[i][r >> 1], 0.f);
                Es[rl * EPITCH + cl] = logf((dist + 1.0f) / (dist + EPS));
            }
    __syncthreads();

    // ---- coalesced store ----
    if (tid < 224) {
        const int col  = tid % NT;
        const int row0 = tid / NT;
        const int n    = nb + col;
        if (n < HW_SZ) {
#pragma unroll 4
            for (int row = row0; row < MT; row += 2) {
                int m = mb + row;
                if (m < P_SZ)
                    out[((size_t)b * P_SZ + m) * HW_SZ + n] = Es[row * EPITCH + col];
            }
        }
    }
}

extern "C" void kernel_launch(void* const* d_in, const int* in_sizes, int n_in,
                              void* d_out, int out_size) {
    const float* x = (const float*)d_in[0];   // (64, 512, 14, 14)
    const float* p = (const float*)d_in[1];   // (2000, 512, 1, 1)
    float* out = (float*)d_out;               // (64, 2000, 14, 14)

    x_conv<<<dim3(7, B_SZ), 256>>>(x);
    p_conv<<<250, 256>>>(p);

    __nv_bfloat16 *xt, *pb;
    cudaGetSymbolAddress((void**)&xt, g_xb16t);
    cudaGetSymbolAddress((void**)&pb, g_pb16);

    cudaFuncSetAttribute(proto_mma, cudaFuncAttributeMaxDynamicSharedMemorySize, SMEM_BYTES);
    dim3 grid(2, 16, B_SZ);
    proto_mma<<<grid, 256, SMEM_BYTES>>>(xt, pb, out);
}

// round 8
// speedup vs baseline: 1.5430x; 1.0938x over previous
#include <cuda_runtime.h>
#include <cuda_bf16.h>
#include <cstdint>
#include <math.h>

#define EPS 1e-4f
#define B_SZ   64
#define C_SZ   512
#define HW_SZ  196
#define P_SZ   2000
#define MT     128
#define NT     112
#define KC     64
#define NSTAGE 8
#define NBUF   3
#define EPITCH 113

#define AP 144                         // A row pitch bytes (64 bf16 = 128B data + 16 pad)
#define BP 144                         // B row pitch bytes
#define A_STG_B (MT*AP)                // 18432
#define B_STG_B (NT*BP)                // 16128
#define STG_B   (A_STG_B + B_STG_B)    // 34560
#define SMEM_BYTES (NBUF*STG_B)        // 103680

// global scratch (no cudaMalloc allowed); .bss zero-init
__device__ __nv_bfloat16 g_xb16t[B_SZ * HW_SZ * C_SZ];   // [b][hw][c]
__device__ __nv_bfloat16 g_pb16[2048 * C_SZ];            // [row][c], rows>=2000 zero
__device__ float g_x2[B_SZ * HW_SZ];
__device__ float g_p2[2048];

static __device__ __forceinline__ uint32_t s2u(const void* p) {
    uint32_t a;
    asm("{ .reg .u64 t; cvta.to.shared.u64 t, %1; cvt.u32.u64 %0, t; }"
        : "=r"(a) : "l"(p));
    return a;
}

static __device__ __forceinline__ void cpa16(uint32_t dst, const void* src, int sz) {
    asm volatile("cp.async.cg.shared.global [%0], [%1], 16, %2;"
                 :: "r"(dst), "l"(src), "r"(sz));
}

static __device__ __forceinline__ void ldsm4(uint32_t& r0, uint32_t& r1,
                                             uint32_t& r2, uint32_t& r3, uint32_t a) {
    asm volatile("ldmatrix.sync.aligned.m8n8.x4.shared.b16 {%0,%1,%2,%3}, [%4];"
                 : "=r"(r0), "=r"(r1), "=r"(r2), "=r"(r3) : "r"(a));
}

static __device__ __forceinline__ void ldsm2(uint32_t& r0, uint32_t& r1, uint32_t a) {
    asm volatile("ldmatrix.sync.aligned.m8n8.x2.shared.b16 {%0,%1}, [%2];"
                 : "=r"(r0), "=r"(r1) : "r"(a));
}

static __device__ __forceinline__ void mma_bf16(
    float& c0, float& c1, float& c2, float& c3,
    uint32_t a0, uint32_t a1, uint32_t a2, uint32_t a3,
    uint32_t b0, uint32_t b1)
{
    asm volatile(
        "mma.sync.aligned.m16n8k16.row.col.f32.bf16.bf16.f32 "
        "{%0,%1,%2,%3}, {%4,%5,%6,%7}, {%8,%9}, {%0,%1,%2,%3};"
        : "+f"(c0), "+f"(c1), "+f"(c2), "+f"(c3)
        : "r"(a0), "r"(a1), "r"(a2), "r"(a3), "r"(b0), "r"(b1));
}

// ---- prefix 1: x -> bf16 transposed [b][hw][c], + exact fp32 x2 ----
__global__ __launch_bounds__(256) void x_conv(const float* __restrict__ x) {
    __shared__ float sm[64 * 29];
    __shared__ float ps[28 * 65];
    const int tid = threadIdx.x;
    const int b   = blockIdx.y;
    const int hw0 = blockIdx.x * 28;
    const float* xb = x + (size_t)b * C_SZ * HW_SZ;
    __nv_bfloat16* ob = g_xb16t + ((size_t)b * HW_SZ + hw0) * C_SZ;

    for (int c0 = 0; c0 < C_SZ; c0 += 64) {
#pragma unroll
        for (int l = 0; l < 7; l++) {
            int idx = tid + l * 256;
            int c = idx / 28, hw = idx - c * 28;
            sm[c * 29 + hw] = xb[(size_t)(c0 + c) * HW_SZ + hw0 + hw];
        }
        __syncthreads();
#pragma unroll
        for (int l = 0; l < 7; l++) {
            int idx = tid + l * 256;
            int hw = idx >> 6, c = idx & 63;
            float v = sm[c * 29 + hw];
            ob[(size_t)hw * C_SZ + c0 + c] = __float2bfloat16(v);
            if (c0 == 0) ps[hw * 65 + c] = v * v;
            else         ps[hw * 65 + c] += v * v;
        }
        __syncthreads();
    }
    if (tid < 28) {
        float s = 0.f;
#pragma unroll
        for (int c = 0; c < 64; c++) s += ps[tid * 65 + c];
        g_x2[b * HW_SZ + hw0 + tid] = s;
    }
}

// ---- prefix 2: p -> bf16 + p2 ----
__global__ __launch_bounds__(256) void p_conv(const float* __restrict__ p) {
    int row  = blockIdx.x * 8 + (threadIdx.x >> 5);
    int lane = threadIdx.x & 31;
    float s = 0.f;
    if (row < P_SZ) {
        const float* pr = p + (size_t)row * C_SZ;
        __nv_bfloat16* pw = g_pb16 + (size_t)row * C_SZ;
#pragma unroll
        for (int t = lane; t < C_SZ; t += 32) {
            float v = pr[t];
            pw[t] = __float2bfloat16(v);
            s = fmaf(v, v, s);
        }
    }
#pragma unroll
    for (int o = 16; o > 0; o >>= 1)
        s += __shfl_down_sync(0xffffffffu, s, o);
    if (row < P_SZ && lane == 0) g_p2[row] = s;
}

// ---- main fused bf16 GEMM + epilogue ----
__global__ __launch_bounds__(256, 2) void proto_mma(
    const __nv_bfloat16* __restrict__ xt,
    const __nv_bfloat16* __restrict__ pb,
    float* __restrict__ out)
{
    extern __shared__ char smc[];
    const uint32_t sb = s2u(smc);
    const int tid  = threadIdx.x;
    const int wid  = tid >> 5;
    const int lane = tid & 31;
    const int qr   = lane >> 2;
    const int qc   = lane & 3;
    const int nb   = blockIdx.x * NT;
    const int mb   = blockIdx.y * MT;
    const int b    = blockIdx.z;
    const int mw   = (wid >> 1) * 32;
    const int nw   = (wid & 1) * 56;
    const __nv_bfloat16* xbase = xt + (size_t)b * HW_SZ * C_SZ;

    // ldmatrix lane address components
    const int lrow  = mw + (lane & 7) + 8 * ((lane >> 3) & 1);
    const int lcolB = (lane >> 4) << 4;                       // A: +16B col-half
    const int brow  = nw + ((lane >> 4) << 3) + (lane & 7);   // B: n row
    const int bhalf = ((lane >> 3) & 1) << 4;                 // B: +16B k-half

    // loader coords (KC=64: 8x16B chunks per row)
    const int a_row = tid >> 3, a_c = tid & 7;
    const __nv_bfloat16* a_src = pb + (size_t)(mb + a_row) * C_SZ + a_c * 8;

    float acc[2][7][4];
#pragma unroll
    for (int i = 0; i < 2; i++)
#pragma unroll
        for (int j = 0; j < 7; j++)
#pragma unroll
            for (int r = 0; r < 4; r++) acc[i][j][r] = 0.f;

    auto load_stage = [&](int s) {
        const int buf = s % NBUF;
        const int kt  = s * KC;
        const uint32_t sA = sb + buf * STG_B;
        const uint32_t sB = sA + A_STG_B;
        // A: 128 rows x 8 chunks = 1024, 4/thread (rows step 32)
#pragma unroll
        for (int l = 0; l < 4; l++) {
            cpa16(sA + (a_row + l * 32) * AP + a_c * 16,
                  a_src + (size_t)l * 32 * C_SZ + kt, 16);
        }
        // B: 112 rows x 8 chunks = 896
#pragma unroll
        for (int l = 0; l < 4; l++) {
            int idx = tid + l * 256;
            if (idx < 896) {
                int n = idx >> 3, c = idx & 7;
                int hw = nb + n;
                int sz = (hw < HW_SZ) ? 16 : 0;
                cpa16(sB + n * BP + c * 16,
                      xbase + (size_t)hw * C_SZ + kt + c * 8, sz);
            }
        }
    };

    load_stage(0);
    asm volatile("cp.async.commit_group;" ::: "memory");
    load_stage(1);
    asm volatile("cp.async.commit_group;" ::: "memory");

    for (int s = 0; s < NSTAGE; s++) {
        asm volatile("cp.async.wait_group 1;" ::: "memory");
        __syncthreads();
        if (s + 2 < NSTAGE) load_stage(s + 2);
        asm volatile("cp.async.commit_group;" ::: "memory");

        const int buf = s % NBUF;
        const uint32_t sA = sb + buf * STG_B;
        const uint32_t sB = sA + A_STG_B;
        const uint32_t aAddr = sA + lrow * AP + lcolB;
        const uint32_t bAddr = sB + brow * BP + bhalf;

#pragma unroll
        for (int ks = 0; ks < 4; ks++) {
            const int ko = ks * 32;
            uint32_t af[2][4];
            ldsm4(af[0][0], af[0][1], af[0][2], af[0][3], aAddr + ko);
            ldsm4(af[1][0], af[1][1], af[1][2], af[1][3], aAddr + 16 * AP + ko);
            uint32_t bbf[7][2];
#pragma unroll
            for (int jp = 0; jp < 3; jp++)
                ldsm4(bbf[2*jp][0], bbf[2*jp][1], bbf[2*jp+1][0], bbf[2*jp+1][1],
                      bAddr + jp * 16 * BP + ko);
            ldsm2(bbf[6][0], bbf[6][1], bAddr + 48 * BP + ko);
#pragma unroll
            for (int j = 0; j < 7; j++) {
                mma_bf16(acc[0][j][0], acc[0][j][1], acc[0][j][2], acc[0][j][3],
                         af[0][0], af[0][1], af[0][2], af[0][3], bbf[j][0], bbf[j][1]);
                mma_bf16(acc[1][j][0], acc[1][j][1], acc[1][j][2], acc[1][j][3],
                         af[1][0], af[1][1], af[1][2], af[1][3], bbf[j][0], bbf[j][1]);
            }
        }
    }
    __syncthreads();   // compute done before epilogue reuses smem

    // ---- norms ----
    float pa2v[2][2];
#pragma unroll
    for (int i = 0; i < 2; i++)
#pragma unroll
        for (int h = 0; h < 2; h++) {
            int row = mb + mw + 16*i + 8*h + qr;
            pa2v[i][h] = (row < P_SZ) ? g_p2[row] : 0.f;
        }
    float x2v[7][2];
#pragma unroll
    for (int j = 0; j < 7; j++)
#pragma unroll
        for (int h = 0; h < 2; h++) {
            int n = nb + nw + 8*j + qc*2 + h;
            x2v[j][h] = (n < HW_SZ) ? g_x2[b * HW_SZ + n] : 0.f;
        }

    // ---- epilogue -> smem transpose ----
    float* Es = (float*)smc;   // 128 x 113 fp32 = 57856 <= 103680
#pragma unroll
    for (int i = 0; i < 2; i++)
#pragma unroll
        for (int j = 0; j < 7; j++)
#pragma unroll
            for (int r = 0; r < 4; r++) {
                int rl = mw + 16*i + qr + (r >> 1) * 8;
                int cl = nw + 8*j + qc * 2 + (r & 1);
                float dist = fmaxf(x2v[j][r & 1] - 2.f * acc[i][j][r] + pa2v[i][r >> 1], 0.f);
                Es[rl * EPITCH + cl] = logf((dist + 1.0f) / (dist + EPS));
            }
    __syncthreads();

    // ---- coalesced store ----
    if (tid < 224) {
        const int col  = tid % NT;
        const int row0 = tid / NT;
        const int n    = nb + col;
        if (n < HW_SZ) {
#pragma unroll 4
            for (int row = row0; row < MT; row += 2) {
                int m = mb + row;
                if (m < P_SZ)
                    out[((size_t)b * P_SZ + m) * HW_SZ + n] = Es[row * EPITCH + col];
            }
        }
    }
}

extern "C" void kernel_launch(void* const* d_in, const int* in_sizes, int n_in,
                              void* d_out, int out_size) {
    const float* x = (const float*)d_in[0];   // (64, 512, 14, 14)
    const float* p = (const float*)d_in[1];   // (2000, 512, 1, 1)
    float* out = (float*)d_out;               // (64, 2000, 14, 14)

    x_conv<<<dim3(7, B_SZ), 256>>>(x);
    p_conv<<<250, 256>>>(p);

    __nv_bfloat16 *xt, *pb;
    cudaGetSymbolAddress((void**)&xt, g_xb16t);
    cudaGetSymbolAddress((void**)&pb, g_pb16);

    cudaFuncSetAttribute(proto_mma, cudaFuncAttributeMaxDynamicSharedMemorySize, SMEM_BYTES);
    dim3 grid(2, 16, B_SZ);
    proto_mma<<<grid, 256, SMEM_BYTES>>>(xt, pb, out);
}